// round 5
// baseline (speedup 1.0000x reference)
#include <cuda_runtime.h>
#include <cuda_bf16.h>
#include <cstdint>

// Winograd F(2x2,3x3): N=16, C=128, O=128, H=W=112, pad=1
#define NB 16
#define CD 128
#define OD 128
#define HH 112
#define NT 56
#define TPI (NT*NT)            // 3136 tiles per image
#define TILES (NB*TPI)         // 50176 total tiles

// Scratch (allocation-free): U/V as bf16 hi|lo. No M scratch — fused epilogue.
__device__ unsigned short g_Ub[16 * OD * 256];            //  1 MB  U[p][o][c_hi|c_lo]
__device__ unsigned short g_Vb[(size_t)16 * TILES * 256]; // 411 MB V[p][tile][c_hi|c_lo]

__constant__ float c_AT0[4] = {1.f, 1.f, 1.f, 0.f};
__constant__ float c_AT1[4] = {0.f, 1.f, -1.f, -1.f};

__device__ __forceinline__ uint32_t smem_to_u32(const void* p) {
    uint32_t a;
    asm("{ .reg .u64 t; cvta.to.shared.u64 t, %1; cvt.u32.u64 %0, t; }" : "=r"(a) : "l"(p));
    return a;
}

// ldmatrix x4 (sm_75+)
#define LDSM4(r, addr) \
    asm volatile("ldmatrix.sync.aligned.m8n8.x4.shared.b16 {%0,%1,%2,%3}, [%4];" \
        : "=r"((r)[0]), "=r"((r)[1]), "=r"((r)[2]), "=r"((r)[3]) : "r"(addr))

// bf16 HMMA (sm_80+)
#define MMA_BF16(d, a, b) \
    asm volatile("mma.sync.aligned.m16n8k16.row.col.f32.bf16.bf16.f32 " \
        "{%0,%1,%2,%3},{%4,%5,%6,%7},{%8,%9},{%0,%1,%2,%3};" \
        : "+f"((d)[0]), "+f"((d)[1]), "+f"((d)[2]), "+f"((d)[3]) \
        : "r"((a)[0]), "r"((a)[1]), "r"((a)[2]), "r"((a)[3]), \
          "r"((b)[0]), "r"((b)[1]))

// cp.async (sm_80+)
#define CP16(dst, src) \
    asm volatile("cp.async.cg.shared.global [%0], [%1], 16;" :: "r"(dst), "l"(src) : "memory")
#define CP_COMMIT() asm volatile("cp.async.commit_group;" ::: "memory")
#define CP_WAIT0()  asm volatile("cp.async.wait_group 0;" ::: "memory")

__device__ __forceinline__ uint32_t split_pack(float v) {
    __nv_bfloat16 h = __float2bfloat16(v);
    float hf = __bfloat162float(h);
    __nv_bfloat16 l = __float2bfloat16(v - hf);
    uint16_t hu = __bfloat16_as_ushort(h);
    uint16_t lu = __bfloat16_as_ushort(l);
    return (uint32_t)hu | ((uint32_t)lu << 16);
}

// SMEM 512B-row swizzle: 32x 16B units/row; keeps bits[4:3], XORs low3 with row
__device__ __forceinline__ uint32_t swz(uint32_t u, uint32_t row) {
    return (u & 24u) | ((u ^ row) & 7u);
}

// ---------------- K1: weight transform  U = G g G^T -> bf16 hi|lo ------------
__global__ void k_wt(const float* __restrict__ w) {
    int tid = blockIdx.x * 128 + threadIdx.x;   // 16384 threads: (c,o)
    int o = tid & 127;
    int c = tid >> 7;
    const float* g = w + ((size_t)o * CD + c) * 9;
    float gm[3][3];
#pragma unroll
    for (int i = 0; i < 3; i++)
#pragma unroll
        for (int j = 0; j < 3; j++) gm[i][j] = g[i * 3 + j];

    float t[4][3];
#pragma unroll
    for (int k = 0; k < 3; k++) {
        t[0][k] = gm[0][k];
        t[1][k] = 0.5f * (gm[0][k] + gm[1][k] + gm[2][k]);
        t[2][k] = 0.5f * (gm[0][k] - gm[1][k] + gm[2][k]);
        t[3][k] = gm[2][k];
    }
#pragma unroll
    for (int i = 0; i < 4; i++) {
        float u[4];
        u[0] = t[i][0];
        u[1] = 0.5f * (t[i][0] + t[i][1] + t[i][2]);
        u[2] = 0.5f * (t[i][0] - t[i][1] + t[i][2]);
        u[3] = t[i][2];
#pragma unroll
        for (int j = 0; j < 4; j++) {
            int p = i * 4 + j;
            uint32_t hl = split_pack(u[j]);
            unsigned short* up = g_Ub + ((size_t)(p * OD + o)) * 256;
            up[c] = (unsigned short)(hl & 0xffff);
            up[128 + c] = (unsigned short)(hl >> 16);
        }
    }
}

// ---------------- K2: input transform -> V[p][tile][c_hi|c_lo] bf16 ----------
__global__ void __launch_bounds__(256) k_in(const float* __restrict__ x) {
    extern __shared__ uint32_t S[];   // [32 c][16 p][32 tiles] = 64KB
    const int tid = threadIdx.x;
    const int lane = tid & 31;
    const int cg8 = tid >> 5;

    {
        int tile = blockIdx.x * 32 + lane;
        int n = tile / TPI;
        int r = tile - n * TPI;
        int ty = r / NT;
        int tx = r - ty * NT;
        int r0 = 2 * ty - 1, c0 = 2 * tx - 1;
        const float* xn = x + (size_t)n * CD * (HH * HH);

#pragma unroll
        for (int cs = 0; cs < 4; cs++) {
            int cl = cg8 * 4 + cs;
            int c = blockIdx.y * 32 + cl;
            const float* xp = xn + (size_t)c * (HH * HH);
            float d[4][4];
#pragma unroll
            for (int ii = 0; ii < 4; ii++) {
                int rr = r0 + ii;
                bool okr = ((unsigned)rr < HH);
#pragma unroll
                for (int jj = 0; jj < 4; jj++) {
                    int cc = c0 + jj;
                    d[ii][jj] = (okr && (unsigned)cc < HH) ? xp[rr * HH + cc] : 0.0f;
                }
            }
            float t[4][4];
#pragma unroll
            for (int j = 0; j < 4; j++) {
                t[0][j] = d[0][j] - d[2][j];
                t[1][j] = d[1][j] + d[2][j];
                t[2][j] = d[2][j] - d[1][j];
                t[3][j] = d[1][j] - d[3][j];
            }
#pragma unroll
            for (int i = 0; i < 4; i++) {
                float v0 = t[i][0] - t[i][2];
                float v1 = t[i][1] + t[i][2];
                float v2 = t[i][2] - t[i][1];
                float v3 = t[i][1] - t[i][3];
                S[(cl * 16 + (i * 4 + 0)) * 32 + lane] = split_pack(v0);
                S[(cl * 16 + (i * 4 + 1)) * 32 + lane] = split_pack(v1);
                S[(cl * 16 + (i * 4 + 2)) * 32 + lane] = split_pack(v2);
                S[(cl * 16 + (i * 4 + 3)) * 32 + lane] = split_pack(v3);
            }
        }
    }
    __syncthreads();

#pragma unroll
    for (int it = 0; it < 2; it++) {
        int q = it * 256 + tid;      // 512 = 16p * 32tiles
        int p = q >> 5;
        int tl = q & 31;
        int tile = blockIdx.x * 32 + tl;

        uint32_t hp[16], lp[16];
#pragma unroll
        for (int c2 = 0; c2 < 16; c2++) {
            uint32_t u0 = S[((2 * c2) * 16 + p) * 32 + tl];
            uint32_t u1 = S[((2 * c2 + 1) * 16 + p) * 32 + tl];
            hp[c2] = (u0 & 0xffffu) | (u1 << 16);
            lp[c2] = (u0 >> 16) | (u1 & 0xffff0000u);
        }
        unsigned short* vb = g_Vb + ((size_t)p * TILES + tile) * 256 + blockIdx.y * 32;
#pragma unroll
        for (int i = 0; i < 4; i++) {
            *(uint4*)(vb + i * 8) = *((uint4*)hp + i);
            *(uint4*)(vb + 128 + i * 8) = *((uint4*)lp + i);
        }
    }
}

// ---------------- K3: fused GEMM + output transform ---------------------------
// CTA: o=128 x tiles=64, runtime loop p=0..15. Per p: M[p] = U[p]·V[p]
// (bf16 3-split, software-pipelined kc), folded into Y with AT coeffs.
#define STG_BYTES 98304
#define FUSE_SMEM (2 * STG_BYTES)   // 192 KB

// Load one kc's fragments from the swizzled stage
#define LOAD_FRAGS(F_ah, F_al, F_bh, F_bl, aB, bB, kc) do { \
    _Pragma("unroll") \
    for (int m = 0; m < 2; m++) { \
        uint32_t r = rA + m * 16; \
        uint32_t u = 2 * (kc) + uA; \
        LDSM4(F_ah[m], (aB) + r * 512 + (swz(u, r) << 4)); \
        u += 16; \
        LDSM4(F_al[m], (aB) + r * 512 + (swz(u, r) << 4)); \
    } \
    _Pragma("unroll") \
    for (int q = 0; q < 2; q++) { \
        uint32_t r = rB + q * 16; \
        uint32_t u = 2 * (kc) + uB; \
        uint32_t t[4]; \
        LDSM4(t, (bB) + r * 512 + (swz(u, r) << 4)); \
        F_bh[2 * q][0] = t[0]; F_bh[2 * q][1] = t[1]; \
        F_bh[2 * q + 1][0] = t[2]; F_bh[2 * q + 1][1] = t[3]; \
        u += 16; \
        LDSM4(t, (bB) + r * 512 + (swz(u, r) << 4)); \
        F_bl[2 * q][0] = t[0]; F_bl[2 * q][1] = t[1]; \
        F_bl[2 * q + 1][0] = t[2]; F_bl[2 * q + 1][1] = t[3]; \
    } \
} while (0)

#define DO_MMAS(F_ah, F_al, F_bh, F_bl) do { \
    _Pragma("unroll") \
    for (int m = 0; m < 2; m++) \
        _Pragma("unroll") \
        for (int nf = 0; nf < 4; nf++) { \
            MMA_BF16(macc[m][nf], F_ah[m], F_bh[nf]); \
            MMA_BF16(macc[m][nf], F_ah[m], F_bl[nf]); \
            MMA_BF16(macc[m][nf], F_al[m], F_bh[nf]); \
        } \
} while (0)

__global__ void __launch_bounds__(256, 1) k_fused(const float* __restrict__ bias,
                                                  float* __restrict__ y) {
    extern __shared__ char sm[];
    const uint32_t base = smem_to_u32(sm);
    const int tid = threadIdx.x;
    const int lane = tid & 31;
    const int wid = tid >> 5;
    const int jb = blockIdx.x * 64;
    const int o0 = (wid & 3) * 32;
    const int n0 = (wid >> 2) * 32;

    // stage p=0 into buffer 0
    {
        const uint4* gA = (const uint4*)g_Ub;
#pragma unroll
        for (int i = 0; i < 16; i++) {
            int g = i * 256 + tid;
            uint32_t row = (uint32_t)g >> 5, u = (uint32_t)g & 31;
            CP16(base + row * 512 + swz(u, row) * 16, gA + g);
        }
        const uint4* gB = (const uint4*)(g_Vb + (size_t)jb * 256);
#pragma unroll
        for (int i = 0; i < 8; i++) {
            int g = i * 256 + tid;
            uint32_t row = (uint32_t)g >> 5, u = (uint32_t)g & 31;
            CP16(base + 65536 + row * 512 + swz(u, row) * 16, gB + g);
        }
        CP_COMMIT();
    }

    float accY[2][2][2][4][4];   // [a][b][m][nf][j] = 128 regs
#pragma unroll
    for (int a = 0; a < 2; a++)
#pragma unroll
        for (int b = 0; b < 2; b++)
#pragma unroll
            for (int m = 0; m < 2; m++)
#pragma unroll
                for (int nf = 0; nf < 4; nf++)
#pragma unroll
                    for (int j = 0; j < 4; j++) accY[a][b][m][nf][j] = 0.0f;

    const uint32_t rA = (uint32_t)(o0 + (lane & 15));
    const uint32_t uA = (uint32_t)(lane >> 4);
    const uint32_t rB = (uint32_t)(n0 + (lane & 7) + ((lane & 16) >> 1));
    const uint32_t uB = (uint32_t)((lane >> 3) & 1);

#pragma unroll 1
    for (int p = 0; p < 16; p++) {
        CP_WAIT0();
        __syncthreads();

        if (p < 15) {   // stage p+1 into the other buffer
            uint32_t nb = base + (uint32_t)((p + 1) & 1) * STG_BYTES;
            const uint4* gA = (const uint4*)(g_Ub + (size_t)(p + 1) * OD * 256);
#pragma unroll
            for (int i = 0; i < 16; i++) {
                int g = i * 256 + tid;
                uint32_t row = (uint32_t)g >> 5, u = (uint32_t)g & 31;
                CP16(nb + row * 512 + swz(u, row) * 16, gA + g);
            }
            const uint4* gB = (const uint4*)(g_Vb + ((size_t)(p + 1) * TILES + jb) * 256);
#pragma unroll
            for (int i = 0; i < 8; i++) {
                int g = i * 256 + tid;
                uint32_t row = (uint32_t)g >> 5, u = (uint32_t)g & 31;
                CP16(nb + 65536 + row * 512 + swz(u, row) * 16, gB + g);
            }
            CP_COMMIT();
        }

        const uint32_t aB = base + (uint32_t)(p & 1) * STG_BYTES;
        const uint32_t bB = aB + 65536;

        float macc[2][4][4];
#pragma unroll
        for (int m = 0; m < 2; m++)
#pragma unroll
            for (int nf = 0; nf < 4; nf++)
#pragma unroll
                for (int j = 0; j < 4; j++) macc[m][nf][j] = 0.0f;

        // software-pipelined kc loop: load F(kc+1) before MMAs of F(kc)
        uint32_t ah0[2][4], al0[2][4], bh0[4][2], bl0[4][2];
        uint32_t ah1[2][4], al1[2][4], bh1[4][2], bl1[4][2];
        LOAD_FRAGS(ah0, al0, bh0, bl0, aB, bB, 0);
#pragma unroll 1
        for (int kc = 0; kc < 8; kc += 2) {
            LOAD_FRAGS(ah1, al1, bh1, bl1, aB, bB, kc + 1);
            DO_MMAS(ah0, al0, bh0, bl0);
            if (kc + 2 < 8) LOAD_FRAGS(ah0, al0, bh0, bl0, aB, bB, kc + 2);
            DO_MMAS(ah1, al1, bh1, bl1);
        }

        // fold M[p] into Y_ab with runtime AT coefficients (uniform-branch skip)
        const int pi = p >> 2, pj = p & 3;
        float cA[2], cB[2];
        cA[0] = c_AT0[pi]; cA[1] = c_AT1[pi];
        cB[0] = c_AT0[pj]; cB[1] = c_AT1[pj];
#pragma unroll
        for (int a = 0; a < 2; a++)
#pragma unroll
            for (int b = 0; b < 2; b++) {
                float c = cA[a] * cB[b];
                if (c != 0.0f) {
#pragma unroll
                    for (int m = 0; m < 2; m++)
#pragma unroll
                        for (int nf = 0; nf < 4; nf++)
#pragma unroll
                            for (int j = 0; j < 4; j++)
                                accY[a][b][m][nf][j] = fmaf(c, macc[m][nf][j],
                                                            accY[a][b][m][nf][j]);
                }
            }
        __syncthreads();
    }

    // Epilogue: bias + direct Y writes (float2 over the b dimension)
#pragma unroll
    for (int m = 0; m < 2; m++) {
#pragma unroll
        for (int h = 0; h < 2; h++) {
            int o = o0 + m * 16 + (lane >> 2) + h * 8;
            float bv = bias[o];
#pragma unroll
            for (int nf = 0; nf < 4; nf++) {
#pragma unroll
                for (int d = 0; d < 2; d++) {
                    int t = jb + n0 + nf * 8 + (lane & 3) * 2 + d;
                    int n = t / TPI;
                    int r = t - n * TPI;
                    int ty = r / NT;
                    int tx = r - ty * NT;
                    float* yp = y + ((size_t)(n * OD + o) * HH + 2 * ty) * HH + 2 * tx;
                    int j = 2 * h + d;
                    float2 v0 = make_float2(accY[0][0][m][nf][j] + bv,
                                            accY[0][1][m][nf][j] + bv);
                    float2 v1 = make_float2(accY[1][0][m][nf][j] + bv,
                                            accY[1][1][m][nf][j] + bv);
                    *(float2*)yp = v0;
                    *(float2*)(yp + HH) = v1;
                }
            }
        }
    }
}

// ---------------- launch --------------------------------------------------------
extern "C" void kernel_launch(void* const* d_in, const int* in_sizes, int n_in,
                              void* d_out, int out_size) {
    const float* x = (const float*)d_in[0];
    const float* w = (const float*)d_in[1];
    const float* bias = (const float*)d_in[2];
    float* y = (float*)d_out;

    cudaFuncSetAttribute(k_in, cudaFuncAttributeMaxDynamicSharedMemorySize, 65536);
    cudaFuncSetAttribute(k_fused, cudaFuncAttributeMaxDynamicSharedMemorySize, FUSE_SMEM);

    k_wt<<<128, 128>>>(w);
    dim3 gi(TILES / 32, 4);                 // 1568 x 4
    k_in<<<gi, 256, 65536>>>(x);
    k_fused<<<TILES / 64, 256, FUSE_SMEM>>>(bias, y);   // 784 CTAs
}

// round 6
// speedup vs baseline: 1.0476x; 1.0476x over previous
#include <cuda_runtime.h>
#include <cuda_bf16.h>
#include <cstdint>

// Winograd F(2x2,3x3): N=16, C=128, O=128, H=W=112, pad=1
#define NB 16
#define CD 128
#define OD 128
#define HH 112
#define NT 56
#define TPI (NT*NT)            // 3136 tiles per image
#define TILES (NB*TPI)         // 50176 total tiles

// Scratch (allocation-free): U/V as bf16 hi|lo. No M scratch — fused epilogue.
__device__ unsigned short g_Ub[16 * OD * 256];            //  1 MB  U[p][o][c_hi|c_lo]
__device__ unsigned short g_Vb[(size_t)16 * TILES * 256]; // 411 MB V[p][tile][c_hi|c_lo]

__constant__ float c_AT0[4] = {1.f, 1.f, 1.f, 0.f};
__constant__ float c_AT1[4] = {0.f, 1.f, -1.f, -1.f};

__device__ __forceinline__ uint32_t smem_to_u32(const void* p) {
    uint32_t a;
    asm("{ .reg .u64 t; cvta.to.shared.u64 t, %1; cvt.u32.u64 %0, t; }" : "=r"(a) : "l"(p));
    return a;
}

// ldmatrix x4 (sm_75+)
#define LDSM4(r, addr) \
    asm volatile("ldmatrix.sync.aligned.m8n8.x4.shared.b16 {%0,%1,%2,%3}, [%4];" \
        : "=r"((r)[0]), "=r"((r)[1]), "=r"((r)[2]), "=r"((r)[3]) : "r"(addr))

// bf16 HMMA (sm_80+)
#define MMA_BF16(d, a, b) \
    asm volatile("mma.sync.aligned.m16n8k16.row.col.f32.bf16.bf16.f32 " \
        "{%0,%1,%2,%3},{%4,%5,%6,%7},{%8,%9},{%0,%1,%2,%3};" \
        : "+f"((d)[0]), "+f"((d)[1]), "+f"((d)[2]), "+f"((d)[3]) \
        : "r"((a)[0]), "r"((a)[1]), "r"((a)[2]), "r"((a)[3]), \
          "r"((b)[0]), "r"((b)[1]))

// cp.async (sm_80+)
#define CP16(dst, src) \
    asm volatile("cp.async.cg.shared.global [%0], [%1], 16;" :: "r"(dst), "l"(src) : "memory")
#define CP_COMMIT() asm volatile("cp.async.commit_group;" ::: "memory")
#define CP_WAIT0()  asm volatile("cp.async.wait_group 0;" ::: "memory")

__device__ __forceinline__ uint32_t split_pack(float v) {
    __nv_bfloat16 h = __float2bfloat16(v);
    float hf = __bfloat162float(h);
    __nv_bfloat16 l = __float2bfloat16(v - hf);
    uint16_t hu = __bfloat16_as_ushort(h);
    uint16_t lu = __bfloat16_as_ushort(l);
    return (uint32_t)hu | ((uint32_t)lu << 16);
}

// SMEM 512B-row swizzle: 32x 16B units/row; keeps bits[4:3], XORs low3 with row
__device__ __forceinline__ uint32_t swz(uint32_t u, uint32_t row) {
    return (u & 24u) | ((u ^ row) & 7u);
}

// ---------------- K1: weight transform  U = G g G^T -> bf16 hi|lo ------------
__global__ void k_wt(const float* __restrict__ w) {
    int tid = blockIdx.x * 128 + threadIdx.x;   // 16384 threads: (c,o)
    int o = tid & 127;
    int c = tid >> 7;
    const float* g = w + ((size_t)o * CD + c) * 9;
    float gm[3][3];
#pragma unroll
    for (int i = 0; i < 3; i++)
#pragma unroll
        for (int j = 0; j < 3; j++) gm[i][j] = g[i * 3 + j];

    float t[4][3];
#pragma unroll
    for (int k = 0; k < 3; k++) {
        t[0][k] = gm[0][k];
        t[1][k] = 0.5f * (gm[0][k] + gm[1][k] + gm[2][k]);
        t[2][k] = 0.5f * (gm[0][k] - gm[1][k] + gm[2][k]);
        t[3][k] = gm[2][k];
    }
#pragma unroll
    for (int i = 0; i < 4; i++) {
        float u[4];
        u[0] = t[i][0];
        u[1] = 0.5f * (t[i][0] + t[i][1] + t[i][2]);
        u[2] = 0.5f * (t[i][0] - t[i][1] + t[i][2]);
        u[3] = t[i][2];
#pragma unroll
        for (int j = 0; j < 4; j++) {
            int p = i * 4 + j;
            uint32_t hl = split_pack(u[j]);
            unsigned short* up = g_Ub + ((size_t)(p * OD + o)) * 256;
            up[c] = (unsigned short)(hl & 0xffff);
            up[128 + c] = (unsigned short)(hl >> 16);
        }
    }
}

// ---------------- K2: input transform -> V[p][tile][c_hi|c_lo] bf16 ----------
__global__ void __launch_bounds__(256) k_in(const float* __restrict__ x) {
    extern __shared__ uint32_t S[];   // [32 c][16 p][32 tiles] = 64KB
    const int tid = threadIdx.x;
    const int lane = tid & 31;
    const int cg8 = tid >> 5;

    {
        int tile = blockIdx.x * 32 + lane;
        int n = tile / TPI;
        int r = tile - n * TPI;
        int ty = r / NT;
        int tx = r - ty * NT;
        int r0 = 2 * ty - 1, c0 = 2 * tx - 1;
        const float* xn = x + (size_t)n * CD * (HH * HH);

#pragma unroll
        for (int cs = 0; cs < 4; cs++) {
            int cl = cg8 * 4 + cs;
            int c = blockIdx.y * 32 + cl;
            const float* xp = xn + (size_t)c * (HH * HH);
            float d[4][4];
#pragma unroll
            for (int ii = 0; ii < 4; ii++) {
                int rr = r0 + ii;
                bool okr = ((unsigned)rr < HH);
#pragma unroll
                for (int jj = 0; jj < 4; jj++) {
                    int cc = c0 + jj;
                    d[ii][jj] = (okr && (unsigned)cc < HH) ? xp[rr * HH + cc] : 0.0f;
                }
            }
            float t[4][4];
#pragma unroll
            for (int j = 0; j < 4; j++) {
                t[0][j] = d[0][j] - d[2][j];
                t[1][j] = d[1][j] + d[2][j];
                t[2][j] = d[2][j] - d[1][j];
                t[3][j] = d[1][j] - d[3][j];
            }
#pragma unroll
            for (int i = 0; i < 4; i++) {
                float v0 = t[i][0] - t[i][2];
                float v1 = t[i][1] + t[i][2];
                float v2 = t[i][2] - t[i][1];
                float v3 = t[i][1] - t[i][3];
                S[(cl * 16 + (i * 4 + 0)) * 32 + lane] = split_pack(v0);
                S[(cl * 16 + (i * 4 + 1)) * 32 + lane] = split_pack(v1);
                S[(cl * 16 + (i * 4 + 2)) * 32 + lane] = split_pack(v2);
                S[(cl * 16 + (i * 4 + 3)) * 32 + lane] = split_pack(v3);
            }
        }
    }
    __syncthreads();

#pragma unroll
    for (int it = 0; it < 2; it++) {
        int q = it * 256 + tid;      // 512 = 16p * 32tiles
        int p = q >> 5;
        int tl = q & 31;
        int tile = blockIdx.x * 32 + tl;

        uint32_t hp[16], lp[16];
#pragma unroll
        for (int c2 = 0; c2 < 16; c2++) {
            uint32_t u0 = S[((2 * c2) * 16 + p) * 32 + tl];
            uint32_t u1 = S[((2 * c2 + 1) * 16 + p) * 32 + tl];
            hp[c2] = (u0 & 0xffffu) | (u1 << 16);
            lp[c2] = (u0 >> 16) | (u1 & 0xffff0000u);
        }
        unsigned short* vb = g_Vb + ((size_t)p * TILES + tile) * 256 + blockIdx.y * 32;
#pragma unroll
        for (int i = 0; i < 4; i++) {
            *(uint4*)(vb + i * 8) = *((uint4*)hp + i);
            *(uint4*)(vb + 128 + i * 8) = *((uint4*)lp + i);
        }
    }
}

// ---------------- K3: fused GEMM + output transform ---------------------------
// CTA: o=128 x tiles=64, 512 threads (16 warps, warp tile 32o x 16t).
// Runtime p loop; per p: M[p] = U[p]·V[p] (bf16 3-split), fold into Y.
#define STG_BYTES 98304
#define FUSE_SMEM (2 * STG_BYTES)   // 192 KB

__global__ void __launch_bounds__(512, 1) k_fused(const float* __restrict__ bias,
                                                  float* __restrict__ y) {
    extern __shared__ char sm[];
    const uint32_t base = smem_to_u32(sm);
    const int tid = threadIdx.x;
    const int lane = tid & 31;
    const int wid = tid >> 5;
    const int jb = blockIdx.x * 64;
    const int o0 = (wid & 3) * 32;    // 4 o-groups
    const int n0 = (wid >> 2) * 16;   // 4 t-groups

    // stage p=0 into buffer 0
    {
        const uint4* gA = (const uint4*)g_Ub;
#pragma unroll
        for (int i = 0; i < 8; i++) {
            int g = i * 512 + tid;
            uint32_t row = (uint32_t)g >> 5, u = (uint32_t)g & 31;
            CP16(base + row * 512 + swz(u, row) * 16, gA + g);
        }
        const uint4* gB = (const uint4*)(g_Vb + (size_t)jb * 256);
#pragma unroll
        for (int i = 0; i < 4; i++) {
            int g = i * 512 + tid;
            uint32_t row = (uint32_t)g >> 5, u = (uint32_t)g & 31;
            CP16(base + 65536 + row * 512 + swz(u, row) * 16, gB + g);
        }
        CP_COMMIT();
    }

    float accY[2][2][2][2][4];   // [a][b][m][nf][j] = 64 regs
#pragma unroll
    for (int a = 0; a < 2; a++)
#pragma unroll
        for (int b = 0; b < 2; b++)
#pragma unroll
            for (int m = 0; m < 2; m++)
#pragma unroll
                for (int nf = 0; nf < 2; nf++)
#pragma unroll
                    for (int j = 0; j < 4; j++) accY[a][b][m][nf][j] = 0.0f;

    const uint32_t rA = (uint32_t)(o0 + (lane & 15));
    const uint32_t uA = (uint32_t)(lane >> 4);
    const uint32_t rB = (uint32_t)(n0 + (lane & 7) + ((lane & 16) >> 1));
    const uint32_t uB = (uint32_t)((lane >> 3) & 1);

#pragma unroll 1
    for (int p = 0; p < 16; p++) {
        CP_WAIT0();
        __syncthreads();

        if (p < 15) {   // stage p+1 into the other buffer
            uint32_t nb = base + (uint32_t)((p + 1) & 1) * STG_BYTES;
            const uint4* gA = (const uint4*)(g_Ub + (size_t)(p + 1) * OD * 256);
#pragma unroll
            for (int i = 0; i < 8; i++) {
                int g = i * 512 + tid;
                uint32_t row = (uint32_t)g >> 5, u = (uint32_t)g & 31;
                CP16(nb + row * 512 + swz(u, row) * 16, gA + g);
            }
            const uint4* gB = (const uint4*)(g_Vb + ((size_t)(p + 1) * TILES + jb) * 256);
#pragma unroll
            for (int i = 0; i < 4; i++) {
                int g = i * 512 + tid;
                uint32_t row = (uint32_t)g >> 5, u = (uint32_t)g & 31;
                CP16(nb + 65536 + row * 512 + swz(u, row) * 16, gB + g);
            }
            CP_COMMIT();
        }

        const uint32_t aB = base + (uint32_t)(p & 1) * STG_BYTES;
        const uint32_t bB = aB + 65536;

        float macc[2][2][4];
#pragma unroll
        for (int m = 0; m < 2; m++)
#pragma unroll
            for (int nf = 0; nf < 2; nf++)
#pragma unroll
                for (int j = 0; j < 4; j++) macc[m][nf][j] = 0.0f;

#pragma unroll
        for (int kc = 0; kc < 8; kc++) {
            uint32_t ah[2][4], al[2][4], bh[2][2], bl[2][2];
#pragma unroll
            for (int m = 0; m < 2; m++) {
                uint32_t r = rA + m * 16;
                uint32_t u = 2 * kc + uA;
                LDSM4(ah[m], aB + r * 512 + (swz(u, r) << 4));
                u += 16;
                LDSM4(al[m], aB + r * 512 + (swz(u, r) << 4));
            }
            {
                uint32_t r = rB;
                uint32_t u = 2 * kc + uB;
                uint32_t t[4];
                LDSM4(t, bB + r * 512 + (swz(u, r) << 4));
                bh[0][0] = t[0]; bh[0][1] = t[1];
                bh[1][0] = t[2]; bh[1][1] = t[3];
                u += 16;
                LDSM4(t, bB + r * 512 + (swz(u, r) << 4));
                bl[0][0] = t[0]; bl[0][1] = t[1];
                bl[1][0] = t[2]; bl[1][1] = t[3];
            }
#pragma unroll
            for (int m = 0; m < 2; m++)
#pragma unroll
                for (int nf = 0; nf < 2; nf++) {
                    MMA_BF16(macc[m][nf], ah[m], bh[nf]);
                    MMA_BF16(macc[m][nf], ah[m], bl[nf]);
                    MMA_BF16(macc[m][nf], al[m], bh[nf]);
                }
        }

        // fold M[p] into Y_ab with runtime AT coefficients (uniform-branch skip)
        const int pi = p >> 2, pj = p & 3;
        float cA[2], cB[2];
        cA[0] = c_AT0[pi]; cA[1] = c_AT1[pi];
        cB[0] = c_AT0[pj]; cB[1] = c_AT1[pj];
#pragma unroll
        for (int a = 0; a < 2; a++)
#pragma unroll
            for (int b = 0; b < 2; b++) {
                float c = cA[a] * cB[b];
                if (c != 0.0f) {
#pragma unroll
                    for (int m = 0; m < 2; m++)
#pragma unroll
                        for (int nf = 0; nf < 2; nf++)
#pragma unroll
                            for (int j = 0; j < 4; j++)
                                accY[a][b][m][nf][j] = fmaf(c, macc[m][nf][j],
                                                            accY[a][b][m][nf][j]);
                }
            }
        __syncthreads();
    }

    // Epilogue: bias + direct Y writes
#pragma unroll
    for (int m = 0; m < 2; m++) {
#pragma unroll
        for (int h = 0; h < 2; h++) {
            int o = o0 + m * 16 + (lane >> 2) + h * 8;
            float bv = bias[o];
#pragma unroll
            for (int nf = 0; nf < 2; nf++) {
#pragma unroll
                for (int d = 0; d < 2; d++) {
                    int t = jb + n0 + nf * 8 + (lane & 3) * 2 + d;
                    int n = t / TPI;
                    int r = t - n * TPI;
                    int ty = r / NT;
                    int tx = r - ty * NT;
                    float* yp = y + ((size_t)(n * OD + o) * HH + 2 * ty) * HH + 2 * tx;
                    int j = 2 * h + d;
                    float2 v0 = make_float2(accY[0][0][m][nf][j] + bv,
                                            accY[0][1][m][nf][j] + bv);
                    float2 v1 = make_float2(accY[1][0][m][nf][j] + bv,
                                            accY[1][1][m][nf][j] + bv);
                    *(float2*)yp = v0;
                    *(float2*)(yp + HH) = v1;
                }
            }
        }
    }
}

// ---------------- launch --------------------------------------------------------
extern "C" void kernel_launch(void* const* d_in, const int* in_sizes, int n_in,
                              void* d_out, int out_size) {
    const float* x = (const float*)d_in[0];
    const float* w = (const float*)d_in[1];
    const float* bias = (const float*)d_in[2];
    float* y = (float*)d_out;

    cudaFuncSetAttribute(k_in, cudaFuncAttributeMaxDynamicSharedMemorySize, 65536);
    cudaFuncSetAttribute(k_fused, cudaFuncAttributeMaxDynamicSharedMemorySize, FUSE_SMEM);

    k_wt<<<128, 128>>>(w);
    dim3 gi(TILES / 32, 4);                 // 1568 x 4
    k_in<<<gi, 256, 65536>>>(x);
    k_fused<<<TILES / 64, 512, FUSE_SMEM>>>(bias, y);   // 784 CTAs
}